// round 9
// baseline (speedup 1.0000x reference)
#include <cuda_runtime.h>
#include <cstdint>

// ---------------- problem dims ----------------
#define BB   4
#define SS   1024
#define HH   2048
#define NHQ  32
#define NKV  4
#define DH   128
#define NE   32
#define TOPK 8
#define II   768
#define ISD  4096
#define TT   4096          // B*S tokens
#define GQA  8             // NHQ/NKV

// ---------------- scratch (static __device__, no allocs) ----------------
static __device__ float g_x    [(size_t)TT*HH];          // ln1 out
static __device__ float g_q    [(size_t)TT*NHQ*DH];
static __device__ float g_kbuf [(size_t)TT*NKV*DH];
static __device__ float g_vbuf [(size_t)TT*NKV*DH];
static __device__ float g_o    [(size_t)TT*NHQ*DH];
static __device__ float g_h    [(size_t)TT*HH];          // residual after attn
static __device__ float g_x2   [(size_t)TT*HH];          // ln2 out
static __device__ float g_act  [(size_t)TT*TOPK*II];     // moe gate*up
static __device__ float g_ys   [(size_t)TT*TOPK*HH];     // per-slot expert out
static __device__ float g_acts [(size_t)TT*ISD];         // shared gate*up
static __device__ float g_shr  [(size_t)TT*HH];          // shared expert out
static __device__ float g_sig  [TT];
static __device__ int   g_cnt  [NE];
static __device__ int   g_cntT [1];
static __device__ int   g_ptok [(size_t)NE*TT];
static __device__ int   g_ppid [(size_t)NE*TT];
static __device__ float g_pw   [(size_t)NE*TT];
static __device__ int   g_idl  [TT];

// ---------------- helpers ----------------
__device__ __forceinline__ float blockReduceSum(float v) {
    __shared__ float sh[32];
    int lane = threadIdx.x & 31, wid = threadIdx.x >> 5;
#pragma unroll
    for (int o = 16; o > 0; o >>= 1) v += __shfl_xor_sync(0xffffffffu, v, o);
    if (lane == 0) sh[wid] = v;
    __syncthreads();
    int nw = blockDim.x >> 5;
    v = (threadIdx.x < nw) ? sh[threadIdx.x] : 0.f;
    if (wid == 0) {
#pragma unroll
        for (int o = 16; o > 0; o >>= 1) v += __shfl_xor_sync(0xffffffffu, v, o);
        if (lane == 0) sh[0] = v;
    }
    __syncthreads();
    v = sh[0];
    __syncthreads();
    return v;
}

// tf32 helpers
__device__ __forceinline__ float tf32r(float x) {
    uint32_t r;
    asm("cvt.rna.tf32.f32 %0, %1;" : "=r"(r) : "f"(x));
    return __uint_as_float(r);
}
__device__ __forceinline__ float4 tf32r4(float4 v) {
    return make_float4(tf32r(v.x), tf32r(v.y), tf32r(v.z), tf32r(v.w));
}
__device__ __forceinline__ void mma_tf32(float* c, const uint32_t* a, const uint32_t* b) {
    asm volatile(
        "mma.sync.aligned.m16n8k8.row.col.f32.tf32.tf32.f32 "
        "{%0,%1,%2,%3}, {%4,%5,%6,%7}, {%8,%9}, {%0,%1,%2,%3};\n"
        : "+f"(c[0]), "+f"(c[1]), "+f"(c[2]), "+f"(c[3])
        : "r"(a[0]), "r"(a[1]), "r"(a[2]), "r"(a[3]), "r"(b[0]), "r"(b[1]));
}
__device__ __forceinline__ float ex2f(float x) {
    float r; asm("ex2.approx.ftz.f32 %0, %1;" : "=f"(r) : "f"(x)); return r;
}

// cp.async helpers
__device__ __forceinline__ void cp16(uint32_t s, const void* g) {
    asm volatile("cp.async.ca.shared.global [%0], [%1], 16;\n" :: "r"(s), "l"(g));
}
__device__ __forceinline__ void cp_commit() { asm volatile("cp.async.commit_group;\n"); }
template<int N> __device__ __forceinline__ void cp_wait() {
    asm volatile("cp.async.wait_group %0;\n" :: "n"(N));
}

// ---------------- elementwise / norm kernels ----------------
__global__ void rmsnorm_k(const float* __restrict__ in, const float* __restrict__ w,
                          float* __restrict__ out, int ncols) {
    long long row = blockIdx.x;
    const float* x = in + row * (long long)ncols;
    float* o = out + row * (long long)ncols;
    float s = 0.f;
    for (int i = threadIdx.x; i < ncols; i += blockDim.x) { float v = x[i]; s += v * v; }
    s = blockReduceSum(s);
    float r = rsqrtf(s / (float)ncols + 1e-6f);
    for (int i = threadIdx.x; i < ncols; i += blockDim.x) o[i] = x[i] * r * w[i];
}

// per-(token,head) rmsnorm over D=128, then NeoX RoPE. blockDim=128
__global__ void qknorm_rope_k(float* __restrict__ qk, const float* __restrict__ w, int nheads) {
    int idx = blockIdx.x;            // t*nheads + h
    int t = idx / nheads;
    int pos = t & (SS - 1);          // s within batch
    float* x = qk + (size_t)idx * DH;
    int d = threadIdx.x;
    float v = x[d];
    float ss = v * v;
#pragma unroll
    for (int o = 16; o > 0; o >>= 1) ss += __shfl_xor_sync(0xffffffffu, ss, o);
    __shared__ float wsum[4];
    if ((d & 31) == 0) wsum[d >> 5] = ss;
    __syncthreads();
    float tot = wsum[0] + wsum[1] + wsum[2] + wsum[3];
    float r = rsqrtf(tot * (1.0f / DH) + 1e-6f);
    float xn = v * r * w[d];
    __shared__ float xs[DH];
    xs[d] = xn;
    __syncthreads();
    int fi = d & 63;
    float ang = (float)pos * expf(-0.215867352778f * (float)fi);
    float c = cosf(ang), s = sinf(ang);
    float rot = (d < 64) ? -xs[d + 64] : xs[d - 64];
    x[d] = xn * c + rot * s;
}

__global__ void init_k(int* __restrict__ idl, int* __restrict__ cntT) {
    int i = blockIdx.x * blockDim.x + threadIdx.x;
    if (i < TT) idl[i] = i;
    if (i == 0) cntT[0] = TT;
}

// router: logits = x2 @ Wr, softmax, top-8, normalize, append to expert lists. blockDim=128
__global__ void router_k(const float* __restrict__ X, const float* __restrict__ Wr,
                         int* __restrict__ cnt, int* __restrict__ gtok,
                         int* __restrict__ gpid, float* __restrict__ gpw) {
    int t = blockIdx.x;
    const float* x = X + (size_t)t * HH;
    float part[NE];
#pragma unroll
    for (int e = 0; e < NE; e++) part[e] = 0.f;
    for (int k = threadIdx.x; k < HH; k += 128) {
        float xv = x[k];
        const float* wr = Wr + (size_t)k * NE;
#pragma unroll
        for (int e = 0; e < NE; e++) part[e] += xv * wr[e];
    }
    __shared__ float sh[NE * 128];
#pragma unroll
    for (int e = 0; e < NE; e++) sh[e * 128 + threadIdx.x] = part[e];
    __syncthreads();
    __shared__ float logits[NE];
    if (threadIdx.x < NE) {
        float s = 0.f;
        for (int i = 0; i < 128; i++) s += sh[threadIdx.x * 128 + i];
        logits[threadIdx.x] = s;
    }
    __syncthreads();
    if (threadIdx.x == 0) {
        float mx = -3.0e38f;
        for (int e = 0; e < NE; e++) mx = fmaxf(mx, logits[e]);
        float p[NE], se = 0.f;
        for (int e = 0; e < NE; e++) { p[e] = expf(logits[e] - mx); se += p[e]; }
        float inv = 1.f / se;
        for (int e = 0; e < NE; e++) p[e] *= inv;
        int idx[TOPK]; float val[TOPK]; float vs = 0.f;
        bool used[NE];
        for (int e = 0; e < NE; e++) used[e] = false;
        for (int s = 0; s < TOPK; s++) {
            float bv = -1.f; int bi = 0;
            for (int e = 0; e < NE; e++)
                if (!used[e] && p[e] > bv) { bv = p[e]; bi = e; }
            used[bi] = true; idx[s] = bi; val[s] = bv; vs += bv;
        }
        float invs = 1.f / vs;
        for (int s = 0; s < TOPK; s++) {
            int e = idx[s];
            int pos = atomicAdd(&cnt[e], 1);
            gtok[(size_t)e * TT + pos] = t;
            gpid[(size_t)e * TT + pos] = t * TOPK + s;
            gpw [(size_t)e * TT + pos] = val[s] * invs;
        }
    }
}

__global__ void sig_k(const float* __restrict__ X, const float* __restrict__ Wshg,
                      float* __restrict__ sig) {
    int t = blockIdx.x;
    const float* x = X + (size_t)t * HH;
    float s = 0.f;
    for (int i = threadIdx.x; i < HH; i += blockDim.x) s += x[i] * Wshg[i];
    s = blockReduceSum(s);
    if (threadIdx.x == 0) sig[t] = 1.f / (1.f + expf(-s));
}

// float4-vectorized final combine
__global__ void final_k(const float* __restrict__ h, const float* __restrict__ ys,
                        const float* __restrict__ shr, const float* __restrict__ sig,
                        float* __restrict__ out) {
    long long i4 = (long long)blockIdx.x * 256 + threadIdx.x;   // float4 index
    if (i4 >= (long long)TT * HH / 4) return;
    long long base = i4 * 4;
    int t = (int)(base >> 11);
    int n = (int)(base & (HH - 1));
    float4 s = *(const float4*)(h + base);
    const float* yr = ys + ((long long)t * TOPK) * HH + n;
#pragma unroll
    for (int k = 0; k < TOPK; k++) {
        float4 y = *(const float4*)(yr + (long long)k * HH);
        s.x += y.x; s.y += y.y; s.z += y.z; s.w += y.w;
    }
    float sg = sig[t];
    float4 sh = *(const float4*)(shr + base);
    s.x += sh.x * sg; s.y += sh.y * sg; s.z += sh.z * sg; s.w += sh.w * sg;
    *(float4*)(out + base) = s;
}

// ================= TF32 tensor-core GEMM, cp.async 4-stage, single-sync =================
// BM=128, BN=128, BK=16, 256 threads (2m x 4n warps), warp tile 64x32.
#define LDAS 20
#define LDBS 132
#define NST  4
#define TMM_SMEM ((NST*128*LDAS + NST*16*LDBS)*4)

__global__ void __launch_bounds__(256, 2)
tmm_k(const float* __restrict__ A, const float* __restrict__ Bm,
      float* __restrict__ C, const float* __restrict__ addC,
      const int* __restrict__ rows, const float* __restrict__ wgt,
      const int* __restrict__ cnt, int Mfix,
      int N, int K, int lda, int ldc, long long bstride, long long cstrideZ,
      int listld) {
    extern __shared__ float sm[];
    float* As = sm;                        // [NST][128*LDAS]
    float* Bs = sm + NST * 128 * LDAS;     // [NST][16*LDBS]
    __shared__ int   rowIdx[128];
    __shared__ float rowW[128];

    int z = blockIdx.z;
    int mc = cnt ? cnt[z] : Mfix;
    int m0 = blockIdx.y * 128;
    if (m0 >= mc) return;
    int n0 = blockIdx.x * 128;
    const float* Bb = Bm + (long long)z * bstride;
    float* Cz = C + (long long)z * cstrideZ;
    const int*   rl = rows ? rows + (long long)z * listld : nullptr;
    const float* wl = wgt  ? wgt  + (long long)z * listld : nullptr;

    int tid = threadIdx.x;
    if (tid < 128) {
        int m = min(m0 + tid, mc - 1);
        rowIdx[tid] = rl ? rl[m] : m;
        rowW[tid]   = wl ? wl[m] : 1.f;
    }
    __syncthreads();

    int warp = tid >> 5, lane = tid & 31;
    int g = lane >> 2, tc = lane & 3;
    int warpM = (warp & 1) * 64, warpN = (warp >> 1) * 32;

    int aM = tid & 127, aKq = tid >> 7;
    int bR = tid >> 5,  bC = tid & 31;
    const float* aBase = A + (long long)rowIdx[aM] * lda;
    uint32_t asA = (uint32_t)__cvta_generic_to_shared(As);
    uint32_t bsA = (uint32_t)__cvta_generic_to_shared(Bs);
    uint32_t aS0 = asA + (uint32_t)(aM * LDAS + aKq * 4) * 4u;
    uint32_t aS1 = asA + (uint32_t)(aM * LDAS + (aKq + 2) * 4) * 4u;
    uint32_t bS0 = bsA + (uint32_t)(bR * LDBS + bC * 4) * 4u;
    uint32_t bS1 = bsA + (uint32_t)((bR + 8) * LDBS + bC * 4) * 4u;
    const uint32_t aStep = 128u * LDAS * 4u, bStep = 16u * LDBS * 4u;

    float acc[4][4][4] = {};
    int KT = K / 16;

#define TMM_ISSUE(kt, buf) { \
        int k0_ = (kt) * 16; \
        cp16(aS0 + (buf) * aStep, aBase + k0_ + aKq * 4); \
        cp16(aS1 + (buf) * aStep, aBase + k0_ + (aKq + 2) * 4); \
        cp16(bS0 + (buf) * bStep, Bb + (long long)(k0_ + bR) * N + n0 + bC * 4); \
        cp16(bS1 + (buf) * bStep, Bb + (long long)(k0_ + bR + 8) * N + n0 + bC * 4); \
        cp_commit(); }

    TMM_ISSUE(0, 0);
    TMM_ISSUE(1, 1);
    TMM_ISSUE(2, 2);

    for (int kt = 0; kt < KT; kt++) {
        cp_wait<NST - 2>();              // group kt arrived
        __syncthreads();                 // all warps done with buf (kt-1)&3, data visible
        int nb = kt + NST - 1;
        if (nb < KT) TMM_ISSUE(nb, nb & 3);   // overwrites buf (kt-1)&3 — safe after sync
        const float* Ab2 = As + (kt & 3) * 128 * LDAS;
        const float* Bb2 = Bs + (kt & 3) * 16 * LDBS;
#pragma unroll
        for (int ks = 0; ks < 2; ks++) {
            uint32_t afr[4][4], bfr[4][2];
#pragma unroll
            for (int i = 0; i < 4; i++) {
                const float* ar = Ab2 + (warpM + i * 16 + g) * LDAS + ks * 8 + tc;
                afr[i][0] = __float_as_uint(tf32r(ar[0]));
                afr[i][1] = __float_as_uint(tf32r(ar[8 * LDAS]));
                afr[i][2] = __float_as_uint(tf32r(ar[4]));
                afr[i][3] = __float_as_uint(tf32r(ar[8 * LDAS + 4]));
            }
#pragma unroll
            for (int j = 0; j < 4; j++) {
                const float* br = Bb2 + (ks * 8 + tc) * LDBS + warpN + j * 8 + g;
                bfr[j][0] = __float_as_uint(tf32r(br[0]));
                bfr[j][1] = __float_as_uint(tf32r(br[4 * LDBS]));
            }
#pragma unroll
            for (int i = 0; i < 4; i++)
#pragma unroll
                for (int j = 0; j < 4; j++) mma_tf32(acc[i][j], afr[i], bfr[j]);
        }
    }

#pragma unroll
    for (int i = 0; i < 4; i++) {
#pragma unroll
        for (int half = 0; half < 2; half++) {
            int rr = warpM + i * 16 + g + half * 8;
            if (m0 + rr >= mc) continue;
            int grow = rowIdx[rr];
            float w = rowW[rr];
            float* cp = Cz + (long long)grow * ldc + n0 + warpN + 2 * tc;
            const float* ap = addC ? addC + (long long)grow * ldc + n0 + warpN + 2 * tc : nullptr;
#pragma unroll
            for (int j = 0; j < 4; j++) {
                float v0 = acc[i][j][half * 2 + 0] * w;
                float v1 = acc[i][j][half * 2 + 1] * w;
                if (ap) {
                    float2 c0 = *(const float2*)(ap + j * 8);
                    v0 += c0.x; v1 += c0.y;
                }
                *(float2*)(cp + j * 8) = make_float2(v0, v1);
            }
        }
    }
}

// ================= TF32 grouped gate/up GEMM, cp.async 4-stage, single-sync =================
// BM=128, BN=64, BK=16, 256 threads (2m x 4n warps), warp tile 64x16.
#define LDBSG 68
#define TGU_SMEM ((NST*128*LDAS + NST*16*LDBSG*2)*4)

__global__ void __launch_bounds__(256, 2)
tgu_k(const float* __restrict__ X,
      const float* __restrict__ Wg, const float* __restrict__ Wu,
      float* __restrict__ Out,
      const int* __restrict__ gtok, const int* __restrict__ gpid,
      const int* __restrict__ cnt, int Mfix,
      int N, int K, long long wstride, int ldout, int listld) {
    extern __shared__ float sm[];
    float* As  = sm;                            // [NST][128*LDAS]
    float* Bgs = sm + NST * 128 * LDAS;         // [NST][16*LDBSG]
    float* Bus = Bgs + NST * 16 * LDBSG;        // [NST][16*LDBSG]
    __shared__ int rowTok[128];
    __shared__ int rowPid[128];

    int z = blockIdx.z;
    int mc = cnt ? cnt[z] : Mfix;
    int m0 = blockIdx.y * 128;
    if (m0 >= mc) return;
    int n0 = blockIdx.x * 64;
    const float* Wgb = Wg + (long long)z * wstride;
    const float* Wub = Wu + (long long)z * wstride;
    const int* lt = gtok + (long long)z * listld;
    const int* lp = gpid + (long long)z * listld;

    int tid = threadIdx.x;
    if (tid < 128) {
        int m = min(m0 + tid, mc - 1);
        rowTok[tid] = lt[m];
        rowPid[tid] = lp[m];
    }
    __syncthreads();

    int warp = tid >> 5, lane = tid & 31;
    int g = lane >> 2, tc = lane & 3;
    int warpM = (warp & 1) * 64, warpN = (warp >> 1) * 16;

    int aM = tid & 127, aKq = tid >> 7;
    int bR = tid >> 4, bC = tid & 15;
    const float* aBase = X + (long long)rowTok[aM] * K;
    uint32_t asA = (uint32_t)__cvta_generic_to_shared(As);
    uint32_t bgA = (uint32_t)__cvta_generic_to_shared(Bgs);
    uint32_t buA = (uint32_t)__cvta_generic_to_shared(Bus);
    uint32_t aS0 = asA + (uint32_t)(aM * LDAS + aKq * 4) * 4u;
    uint32_t aS1 = asA + (uint32_t)(aM * LDAS + (aKq + 2) * 4) * 4u;
    uint32_t bOf = (uint32_t)(bR * LDBSG + bC * 4) * 4u;
    const uint32_t aStep = 128u * LDAS * 4u, bStep = 16u * LDBSG * 4u;

    float accG[4][2][4] = {}, accU[4][2][4] = {};
    int KT = K / 16;

#define TGU_ISSUE(kt, buf) { \
        int k0_ = (kt) * 16; \
        cp16(aS0 + (buf) * aStep, aBase + k0_ + aKq * 4); \
        cp16(aS1 + (buf) * aStep, aBase + k0_ + (aKq + 2) * 4); \
        cp16(bgA + bOf + (buf) * bStep, Wgb + (long long)(k0_ + bR) * N + n0 + bC * 4); \
        cp16(buA + bOf + (buf) * bStep, Wub + (long long)(k0_ + bR) * N + n0 + bC * 4); \
        cp_commit(); }

    TGU_ISSUE(0, 0);
    TGU_ISSUE(1, 1);
    TGU_ISSUE(2, 2);

    for (int kt = 0; kt < KT; kt++) {
        cp_wait<NST - 2>();
        __syncthreads();
        int nb = kt + NST - 1;
        if (nb < KT) TGU_ISSUE(nb, nb & 3);
        const float* Ab2 = As + (kt & 3) * 128 * LDAS;
        const float* Bg2 = Bgs + (kt & 3) * 16 * LDBSG;
        const float* Bu2 = Bus + (kt & 3) * 16 * LDBSG;
#pragma unroll
        for (int ks = 0; ks < 2; ks++) {
            uint32_t afr[4][4], bgf[2][2], buf2[2][2];
#pragma unroll
            for (int i = 0; i < 4; i++) {
                const float* ar = Ab2 + (warpM + i * 16 + g) * LDAS + ks * 8 + tc;
                afr[i][0] = __float_as_uint(tf32r(ar[0]));
                afr[i][1] = __float_as_uint(tf32r(ar[8 * LDAS]));
                afr[i][2] = __float_as_uint(tf32r(ar[4]));
                afr[i][3] = __float_as_uint(tf32r(ar[8 * LDAS + 4]));
            }
#pragma unroll
            for (int j = 0; j < 2; j++) {
                const float* bgr = Bg2 + (ks * 8 + tc) * LDBSG + warpN + j * 8 + g;
                const float* bur = Bu2 + (ks * 8 + tc) * LDBSG + warpN + j * 8 + g;
                bgf[j][0] = __float_as_uint(tf32r(bgr[0]));
                bgf[j][1] = __float_as_uint(tf32r(bgr[4 * LDBSG]));
                buf2[j][0] = __float_as_uint(tf32r(bur[0]));
                buf2[j][1] = __float_as_uint(tf32r(bur[4 * LDBSG]));
            }
#pragma unroll
            for (int i = 0; i < 4; i++)
#pragma unroll
                for (int j = 0; j < 2; j++) {
                    mma_tf32(accG[i][j], afr[i], bgf[j]);
                    mma_tf32(accU[i][j], afr[i], buf2[j]);
                }
        }
    }

#pragma unroll
    for (int i = 0; i < 4; i++) {
#pragma unroll
        for (int half = 0; half < 2; half++) {
            int rr = warpM + i * 16 + g + half * 8;
            if (m0 + rr >= mc) continue;
            int pid = rowPid[rr];
            float* op = Out + (long long)pid * ldout + n0 + warpN + 2 * tc;
#pragma unroll
            for (int j = 0; j < 2; j++) {
                float g0 = accG[i][j][half * 2 + 0], g1 = accG[i][j][half * 2 + 1];
                float u0 = accU[i][j][half * 2 + 0], u1 = accU[i][j][half * 2 + 1];
                float v0 = (g0 / (1.f + expf(-g0))) * u0;
                float v1 = (g1 / (1.f + expf(-g1))) * u1;
                *(float2*)(op + j * 8) = make_float2(v0, v1);
            }
        }
    }
}

// ================= Fused flash attention (tf32 MMA, online softmax) =================
// One block per (b, head, 128-query tile). 8 warps, each owns 16 query rows.
// KV tiles of 64 keys, double-buffered cp.async; causal.
#define FLDK 132
#define FLDP 68
#define FLASH_SMEM ((4*64*FLDK + 8*16*FLDP)*4)

__global__ void __launch_bounds__(256)
flash_k(const float* __restrict__ Q, const float* __restrict__ Kb,
        const float* __restrict__ Vb, float* __restrict__ O) {
    extern __shared__ float fs[];
    float* Ks = fs;                       // [2][64][FLDK]
    float* Vs = fs + 2 * 64 * FLDK;       // [2][64][FLDK]
    float* Ps = fs + 4 * 64 * FLDK;       // [8][16][FLDP]

    int bh = blockIdx.x;                  // b*NHQ + h
    int b = bh >> 5, hq = bh & 31;
    int kvh = hq >> 3;                    // GQA
    int qb = 7 - blockIdx.y;              // big tiles first
    int tid = threadIdx.x, w = tid >> 5, lane = tid & 31;
    int g = lane >> 2, tc = lane & 3;

    int row0 = qb * 128 + w * 16 + g;
    int row1 = row0 + 8;
    const float* q0 = Q + ((long long)(b * SS + row0) * NHQ + hq) * DH;
    const float* q1 = q0 + (long long)8 * NHQ * DH;
    const float* kbase = Kb + ((long long)b * SS * NKV + kvh) * DH;
    const float* vbase = Vb + ((long long)b * SS * NKV + kvh) * DH;
    uint32_t ksA = (uint32_t)__cvta_generic_to_shared(Ks);
    uint32_t vsA = (uint32_t)__cvta_generic_to_shared(Vs);

    const float scale = 0.08838834764831845f;   // D^-0.5, folded into Q
    uint32_t qf[16][4];
#pragma unroll
    for (int kk = 0; kk < 16; kk++) {
        qf[kk][0] = __float_as_uint(tf32r(q0[kk * 8 + tc] * scale));
        qf[kk][1] = __float_as_uint(tf32r(q1[kk * 8 + tc] * scale));
        qf[kk][2] = __float_as_uint(tf32r(q0[kk * 8 + tc + 4] * scale));
        qf[kk][3] = __float_as_uint(tf32r(q1[kk * 8 + tc + 4] * scale));
    }

    float o[16][4] = {};
    float m0 = -1e30f, m1 = -1e30f, l0 = 0.f, l1 = 0.f;
    float* Pw = Ps + w * 16 * FLDP;
    const float L2E = 1.4426950408889634f;

    int NT = (qb + 1) * 2;

#define FL_LOAD(n0_, buf_) { \
        _Pragma("unroll") \
        for (int p = 0; p < 8; p++) { \
            int c = tid + p * 256; \
            int r = c >> 5, cq = c & 31; \
            long long go = (long long)((n0_) + r) * (NKV * DH) + cq * 4; \
            uint32_t so = (uint32_t)((((buf_) * 64 + r) * FLDK + cq * 4) * 4); \
            cp16(ksA + so, kbase + go); \
            cp16(vsA + so, vbase + go); \
        } \
        cp_commit(); }

    FL_LOAD(0, 0);

    for (int jt = 0; jt < NT; jt++) {
        int n0 = jt * 64;
        if (jt + 1 < NT) { FL_LOAD((jt + 1) * 64, (jt + 1) & 1); cp_wait<1>(); }
        else cp_wait<0>();
        __syncthreads();

        float* Kt = Ks + (jt & 1) * 64 * FLDK;
        float* Vt = Vs + (jt & 1) * 64 * FLDK;
        // in-place tf32 conversion of the arrived tile
#pragma unroll
        for (int p = 0; p < 8; p++) {
            int c = tid + p * 256; int r = c >> 5, cq = c & 31;
            float4* kp = (float4*)(Kt + r * FLDK + cq * 4);
            float4* vp = (float4*)(Vt + r * FLDK + cq * 4);
            *kp = tf32r4(*kp);
            *vp = tf32r4(*vp);
        }
        __syncthreads();

        // S = Q K^T
        float s[8][4] = {};
#pragma unroll
        for (int kk = 0; kk < 16; kk++) {
#pragma unroll
            for (int j2 = 0; j2 < 8; j2++) {
                uint32_t bf[2];
                const float* kr = Kt + (j2 * 8 + g) * FLDK + kk * 8 + tc;
                bf[0] = __float_as_uint(kr[0]);
                bf[1] = __float_as_uint(kr[4]);
                mma_tf32(s[j2], qf[kk], bf);
            }
        }
        // causal mask for diagonal tiles
        if (n0 + 63 > qb * 128) {
#pragma unroll
            for (int j2 = 0; j2 < 8; j2++) {
                int k0 = n0 + j2 * 8 + 2 * tc;
                if (k0     > row0) s[j2][0] = -1e30f;
                if (k0 + 1 > row0) s[j2][1] = -1e30f;
                if (k0     > row1) s[j2][2] = -1e30f;
                if (k0 + 1 > row1) s[j2][3] = -1e30f;
            }
        }
        // online softmax (2 rows per thread)
        float tm0 = -1e30f, tm1 = -1e30f;
#pragma unroll
        for (int j2 = 0; j2 < 8; j2++) {
            tm0 = fmaxf(tm0, fmaxf(s[j2][0], s[j2][1]));
            tm1 = fmaxf(tm1, fmaxf(s[j2][2], s[j2][3]));
        }
        tm0 = fmaxf(tm0, __shfl_xor_sync(0xffffffffu, tm0, 1));
        tm0 = fmaxf(tm0, __shfl_xor_sync(0xffffffffu, tm0, 2));
        tm1 = fmaxf(tm1, __shfl_xor_sync(0xffffffffu, tm1, 1));
        tm1 = fmaxf(tm1, __shfl_xor_sync(0xffffffffu, tm1, 2));
        float mn0 = fmaxf(m0, tm0), mn1 = fmaxf(m1, tm1);
        float ts0 = 0.f, ts1 = 0.f;
#pragma unroll
        for (int j2 = 0; j2 < 8; j2++) {
            s[j2][0] = ex2f((s[j2][0] - mn0) * L2E);
            s[j2][1] = ex2f((s[j2][1] - mn0) * L2E);
            s[j2][2] = ex2f((s[j2][2] - mn1) * L2E);
            s[j2][3] = ex2f((s[j2][3] - mn1) * L2E);
            ts0 += s[j2][0] + s[j2][1];
            ts1 += s[j2][2] + s[j2][3];
        }
        ts0 += __shfl_xor_sync(0xffffffffu, ts0, 1);
        ts0 += __shfl_xor_sync(0xffffffffu, ts0, 2);
        ts1 += __shfl_xor_sync(0xffffffffu, ts1, 1);
        ts1 += __shfl_xor_sync(0xffffffffu, ts1, 2);
        float f0 = ex2f((m0 - mn0) * L2E), f1 = ex2f((m1 - mn1) * L2E);
        l0 = l0 * f0 + ts0; l1 = l1 * f1 + ts1;
        m0 = mn0; m1 = mn1;
#pragma unroll
        for (int j3 = 0; j3 < 16; j3++) {
            o[j3][0] *= f0; o[j3][1] *= f0; o[j3][2] *= f1; o[j3][3] *= f1;
        }
        // P -> smem (tf32), then O += P V
#pragma unroll
        for (int j2 = 0; j2 < 8; j2++) {
            Pw[g * FLDP + j2 * 8 + 2 * tc]           = tf32r(s[j2][0]);
            Pw[g * FLDP + j2 * 8 + 2 * tc + 1]       = tf32r(s[j2][1]);
            Pw[(g + 8) * FLDP + j2 * 8 + 2 * tc]     = tf32r(s[j2][2]);
            Pw[(g + 8) * FLDP + j2 * 8 + 2 * tc + 1] = tf32r(s[j2][3]);
        }
        __syncwarp();
#pragma unroll
        for (int kk2 = 0; kk2 < 8; kk2++) {
            uint32_t af[4];
            af[0] = __float_as_uint(Pw[g * FLDP + kk2 * 8 + tc]);
            af[1] = __float_as_uint(Pw[(g + 8) * FLDP + kk2 * 8 + tc]);
            af[2] = __float_as_uint(Pw[g * FLDP + kk2 * 8 + tc + 4]);
            af[3] = __float_as_uint(Pw[(g + 8) * FLDP + kk2 * 8 + tc + 4]);
#pragma unroll
            for (int j3 = 0; j3 < 16; j3++) {
                uint32_t bf[2];
                bf[0] = __float_as_uint(Vt[(kk2 * 8 + tc) * FLDK + j3 * 8 + g]);
                bf[1] = __float_as_uint(Vt[(kk2 * 8 + tc + 4) * FLDK + j3 * 8 + g]);
                mma_tf32(o[j3], af, bf);
            }
        }
        __syncwarp();
        __syncthreads();
    }

    float il0 = 1.f / l0, il1 = 1.f / l1;
    float* o0 = O + ((long long)(b * SS + row0) * NHQ + hq) * DH;
    float* o1 = o0 + (long long)8 * NHQ * DH;
#pragma unroll
    for (int j3 = 0; j3 < 16; j3++) {
        *(float2*)(o0 + j3 * 8 + 2 * tc) = make_float2(o[j3][0] * il0, o[j3][1] * il0);
        *(float2*)(o1 + j3 * 8 + 2 * tc) = make_float2(o[j3][2] * il1, o[j3][3] * il1);
    }
}

// ---------------- host ----------------
extern "C" void kernel_launch(void* const* d_in, const int* in_sizes, int n_in,
                              void* d_out, int out_size) {
    const float* hidden = (const float*)d_in[0];
    const float* ln1w   = (const float*)d_in[1];
    const float* ln2w   = (const float*)d_in[2];
    const float* qnw    = (const float*)d_in[3];
    const float* knw    = (const float*)d_in[4];
    const float* Wq     = (const float*)d_in[5];
    const float* Wk     = (const float*)d_in[6];
    const float* Wv     = (const float*)d_in[7];
    const float* Wo     = (const float*)d_in[8];
    const float* Wr     = (const float*)d_in[9];
    const float* Weg    = (const float*)d_in[10];
    const float* Weu    = (const float*)d_in[11];
    const float* Wed    = (const float*)d_in[12];
    const float* Wsg    = (const float*)d_in[13];
    const float* Wsu    = (const float*)d_in[14];
    const float* Wsd    = (const float*)d_in[15];
    const float* Wshg   = (const float*)d_in[16];
    float* out = (float*)d_out;

    float *x, *q, *kb, *vb, *o, *h, *x2, *act, *ys, *acts, *shr, *sig, *pw;
    int *cnt, *cntT, *ptok, *ppid, *idl;
    cudaGetSymbolAddress((void**)&x,    g_x);
    cudaGetSymbolAddress((void**)&q,    g_q);
    cudaGetSymbolAddress((void**)&kb,   g_kbuf);
    cudaGetSymbolAddress((void**)&vb,   g_vbuf);
    cudaGetSymbolAddress((void**)&o,    g_o);
    cudaGetSymbolAddress((void**)&h,    g_h);
    cudaGetSymbolAddress((void**)&x2,   g_x2);
    cudaGetSymbolAddress((void**)&act,  g_act);
    cudaGetSymbolAddress((void**)&ys,   g_ys);
    cudaGetSymbolAddress((void**)&acts, g_acts);
    cudaGetSymbolAddress((void**)&shr,  g_shr);
    cudaGetSymbolAddress((void**)&sig,  g_sig);
    cudaGetSymbolAddress((void**)&pw,   g_pw);
    cudaGetSymbolAddress((void**)&cnt,  g_cnt);
    cudaGetSymbolAddress((void**)&cntT, g_cntT);
    cudaGetSymbolAddress((void**)&ptok, g_ptok);
    cudaGetSymbolAddress((void**)&ppid, g_ppid);
    cudaGetSymbolAddress((void**)&idl,  g_idl);

    cudaFuncSetAttribute(tmm_k,   cudaFuncAttributeMaxDynamicSharedMemorySize, TMM_SMEM);
    cudaFuncSetAttribute(tgu_k,   cudaFuncAttributeMaxDynamicSharedMemorySize, TGU_SMEM);
    cudaFuncSetAttribute(flash_k, cudaFuncAttributeMaxDynamicSharedMemorySize, FLASH_SMEM);

    // runtime strides for fused K+V projection (flat device address space)
    long long kvB = (long long)((const char*)Wv - (const char*)Wk) / 4;
    long long kvC = (long long)((char*)vb - (char*)kb) / 4;

    // 1) ln1
    rmsnorm_k<<<TT, 256>>>(hidden, ln1w, x, HH);
    // 2) q + fused k/v projections (tf32 tensor cores, 4-stage cp.async pipeline)
    tmm_k<<<dim3(32, 32, 1), 256, TMM_SMEM>>>(x, Wq, q, nullptr, nullptr, nullptr, nullptr, TT,
        NHQ * DH, HH, HH, NHQ * DH, 0, 0, 0);
    tmm_k<<<dim3(4, 32, 2), 256, TMM_SMEM>>>(x, Wk, kb, nullptr, nullptr, nullptr, nullptr, TT,
        NKV * DH, HH, HH, NKV * DH, kvB, kvC, 0);
    // 3) q/k rmsnorm + rope
    qknorm_rope_k<<<TT * NHQ, DH>>>(q, qnw, NHQ);
    qknorm_rope_k<<<TT * NKV, DH>>>(kb, knw, NKV);
    // 4-6) fused flash attention (causal, online softmax)
    flash_k<<<dim3(BB * NHQ, 8), 256, FLASH_SMEM>>>(q, kb, vb, o);
    // 7) h = hidden + o @ Wo (tf32)
    tmm_k<<<dim3(16, 32, 1), 256, TMM_SMEM>>>(o, Wo, h, hidden, nullptr, nullptr, nullptr, TT,
        HH, NHQ * DH, NHQ * DH, HH, 0, 0, 0);
    // 8) ln2
    rmsnorm_k<<<TT, 256>>>(h, ln2w, x2, HH);
    // 9) routing
    cudaMemsetAsync(cnt, 0, NE * sizeof(int), 0);
    init_k<<<TT / 256, 256>>>(idl, cntT);
    router_k<<<TT, 128>>>(x2, Wr, cnt, ptok, ppid, pw);
    // 10) MoE experts (tf32): gate/up (silu fused) then down (weighted, per-slot)
    tgu_k<<<dim3(II / 64, 32, NE), 256, TGU_SMEM>>>(x2, Weg, Weu, act, ptok, ppid, cnt, 0,
        II, HH, (long long)HH * II, II, TT);
    tmm_k<<<dim3(HH / 128, 32, NE), 256, TMM_SMEM>>>(act, Wed, ys, nullptr, ppid, pw, cnt, 0,
        HH, II, II, HH, (long long)II * HH, 0, TT);
    // 11) shared expert (tf32) via identity lists
    tgu_k<<<dim3(ISD / 64, 32, 1), 256, TGU_SMEM>>>(x2, Wsg, Wsu, acts, idl, idl, cntT, 0,
        ISD, HH, 0, ISD, TT);
    tmm_k<<<dim3(HH / 128, 32, 1), 256, TMM_SMEM>>>(acts, Wsd, shr, nullptr, idl, nullptr, cntT, 0,
        HH, ISD, ISD, HH, 0, 0, TT);
    sig_k<<<TT, 256>>>(x2, Wshg, sig);
    // 12) out = h + sum(slots) + shared*sigmoid
    final_k<<<(TT * HH / 4 + 255) / 256, 256>>>(h, ys, shr, sig, out);
}

// round 14
// speedup vs baseline: 1.0894x; 1.0894x over previous
#include <cuda_runtime.h>
#include <cstdint>

// ---------------- problem dims ----------------
#define BB   4
#define SS   1024
#define HH   2048
#define NHQ  32
#define NKV  4
#define DH   128
#define NE   32
#define TOPK 8
#define II   768
#define ISD  4096
#define TT   4096          // B*S tokens
#define GQA  8             // NHQ/NKV

// ---------------- scratch (static __device__, no allocs) ----------------
static __device__ float g_x    [(size_t)TT*HH];          // ln1 out
static __device__ float g_q    [(size_t)TT*NHQ*DH];
static __device__ float g_kbuf [(size_t)TT*NKV*DH];
static __device__ float g_vbuf [(size_t)TT*NKV*DH];
static __device__ float g_o    [(size_t)TT*NHQ*DH];
static __device__ float g_h    [(size_t)TT*HH];          // residual after attn
static __device__ float g_x2   [(size_t)TT*HH];          // ln2 out
static __device__ float g_act  [(size_t)TT*TOPK*II];     // moe gate*up
static __device__ float g_ys   [(size_t)TT*TOPK*HH];     // per-slot expert out
static __device__ float g_acts [(size_t)TT*ISD];         // shared gate*up
static __device__ float g_shr  [(size_t)TT*HH];          // shared expert out
static __device__ float g_sig  [TT];
static __device__ float g_cosT [(size_t)SS*DH];          // rope LUT
static __device__ float g_sinT [(size_t)SS*DH];
static __device__ int   g_cnt  [NE];
static __device__ int   g_cntT [1];
static __device__ int   g_ptok [(size_t)NE*TT];
static __device__ int   g_ppid [(size_t)NE*TT];
static __device__ float g_pw   [(size_t)NE*TT];
static __device__ int   g_idl  [TT];

// ---------------- helpers ----------------
__device__ __forceinline__ float blockReduceSum(float v) {
    __shared__ float sh[32];
    int lane = threadIdx.x & 31, wid = threadIdx.x >> 5;
#pragma unroll
    for (int o = 16; o > 0; o >>= 1) v += __shfl_xor_sync(0xffffffffu, v, o);
    if (lane == 0) sh[wid] = v;
    __syncthreads();
    int nw = blockDim.x >> 5;
    v = (threadIdx.x < nw) ? sh[threadIdx.x] : 0.f;
    if (wid == 0) {
#pragma unroll
        for (int o = 16; o > 0; o >>= 1) v += __shfl_xor_sync(0xffffffffu, v, o);
        if (lane == 0) sh[0] = v;
    }
    __syncthreads();
    v = sh[0];
    __syncthreads();
    return v;
}

// tf32 helpers
__device__ __forceinline__ float tf32r(float x) {
    uint32_t r;
    asm("cvt.rna.tf32.f32 %0, %1;" : "=r"(r) : "f"(x));
    return __uint_as_float(r);
}
__device__ __forceinline__ float4 tf32r4(float4 v) {
    return make_float4(tf32r(v.x), tf32r(v.y), tf32r(v.z), tf32r(v.w));
}
__device__ __forceinline__ void mma_tf32(float* c, const uint32_t* a, const uint32_t* b) {
    asm volatile(
        "mma.sync.aligned.m16n8k8.row.col.f32.tf32.tf32.f32 "
        "{%0,%1,%2,%3}, {%4,%5,%6,%7}, {%8,%9}, {%0,%1,%2,%3};\n"
        : "+f"(c[0]), "+f"(c[1]), "+f"(c[2]), "+f"(c[3])
        : "r"(a[0]), "r"(a[1]), "r"(a[2]), "r"(a[3]), "r"(b[0]), "r"(b[1]));
}
__device__ __forceinline__ float ex2f(float x) {
    float r; asm("ex2.approx.ftz.f32 %0, %1;" : "=f"(r) : "f"(x)); return r;
}

// cp.async helpers
__device__ __forceinline__ void cp16(uint32_t s, const void* g) {
    asm volatile("cp.async.ca.shared.global [%0], [%1], 16;\n" :: "r"(s), "l"(g));
}
__device__ __forceinline__ void cp_commit() { asm volatile("cp.async.commit_group;\n"); }
template<int N> __device__ __forceinline__ void cp_wait() {
    asm volatile("cp.async.wait_group %0;\n" :: "n"(N));
}

// ---------------- elementwise / norm kernels ----------------
__global__ void rmsnorm_k(const float* __restrict__ in, const float* __restrict__ w,
                          float* __restrict__ out, int ncols) {
    long long row = blockIdx.x;
    const float* x = in + row * (long long)ncols;
    float* o = out + row * (long long)ncols;
    float s = 0.f;
    for (int i = threadIdx.x; i < ncols; i += blockDim.x) { float v = x[i]; s += v * v; }
    s = blockReduceSum(s);
    float r = rsqrtf(s / (float)ncols + 1e-6f);
    for (int i = threadIdx.x; i < ncols; i += blockDim.x) o[i] = x[i] * r * w[i];
}

// rope LUT: cos/sin[pos][d] with the exact same expressions used previously
__global__ void rope_tab_k(float* __restrict__ cosT, float* __restrict__ sinT) {
    int idx = blockIdx.x * 256 + threadIdx.x;     // pos*DH + d
    if (idx >= SS * DH) return;
    int pos = idx >> 7, d = idx & (DH - 1);
    int fi = d & 63;
    float ang = (float)pos * expf(-0.215867352778f * (float)fi);
    cosT[idx] = cosf(ang);
    sinT[idx] = sinf(ang);
}

// per-(token,head) rmsnorm over D=128, then NeoX RoPE via LUT. blockDim=128
__global__ void qknorm_rope_k(float* __restrict__ qk, const float* __restrict__ w,
                              const float* __restrict__ cosT, const float* __restrict__ sinT,
                              int nheads) {
    int idx = blockIdx.x;            // t*nheads + h
    int t = idx / nheads;
    int pos = t & (SS - 1);          // s within batch
    float* x = qk + (size_t)idx * DH;
    int d = threadIdx.x;
    float v = x[d];
    float ss = v * v;
#pragma unroll
    for (int o = 16; o > 0; o >>= 1) ss += __shfl_xor_sync(0xffffffffu, ss, o);
    __shared__ float wsum[4];
    if ((d & 31) == 0) wsum[d >> 5] = ss;
    __syncthreads();
    float tot = wsum[0] + wsum[1] + wsum[2] + wsum[3];
    float r = rsqrtf(tot * (1.0f / DH) + 1e-6f);
    float xn = v * r * w[d];
    __shared__ float xs[DH];
    xs[d] = xn;
    __syncthreads();
    float c = cosT[pos * DH + d];
    float s = sinT[pos * DH + d];
    float rot = (d < 64) ? -xs[d + 64] : xs[d - 64];
    x[d] = xn * c + rot * s;
}

__global__ void init_k(int* __restrict__ idl, int* __restrict__ cntT) {
    int i = blockIdx.x * blockDim.x + threadIdx.x;
    if (i < TT) idl[i] = i;
    if (i == 0) cntT[0] = TT;
}

// router: logits = x2 @ Wr, softmax, top-8, normalize, append to expert lists. blockDim=128
__global__ void router_k(const float* __restrict__ X, const float* __restrict__ Wr,
                         int* __restrict__ cnt, int* __restrict__ gtok,
                         int* __restrict__ gpid, float* __restrict__ gpw) {
    int t = blockIdx.x;
    const float* x = X + (size_t)t * HH;
    float part[NE];
#pragma unroll
    for (int e = 0; e < NE; e++) part[e] = 0.f;
    for (int k = threadIdx.x; k < HH; k += 128) {
        float xv = x[k];
        const float* wr = Wr + (size_t)k * NE;
#pragma unroll
        for (int e = 0; e < NE; e++) part[e] += xv * wr[e];
    }
    __shared__ float sh[NE * 128];
#pragma unroll
    for (int e = 0; e < NE; e++) sh[e * 128 + threadIdx.x] = part[e];
    __syncthreads();
    __shared__ float logits[NE];
    if (threadIdx.x < NE) {
        float s = 0.f;
        for (int i = 0; i < 128; i++) s += sh[threadIdx.x * 128 + i];
        logits[threadIdx.x] = s;
    }
    __syncthreads();
    if (threadIdx.x == 0) {
        float mx = -3.0e38f;
        for (int e = 0; e < NE; e++) mx = fmaxf(mx, logits[e]);
        float p[NE], se = 0.f;
        for (int e = 0; e < NE; e++) { p[e] = expf(logits[e] - mx); se += p[e]; }
        float inv = 1.f / se;
        for (int e = 0; e < NE; e++) p[e] *= inv;
        int idx[TOPK]; float val[TOPK]; float vs = 0.f;
        bool used[NE];
        for (int e = 0; e < NE; e++) used[e] = false;
        for (int s = 0; s < TOPK; s++) {
            float bv = -1.f; int bi = 0;
            for (int e = 0; e < NE; e++)
                if (!used[e] && p[e] > bv) { bv = p[e]; bi = e; }
            used[bi] = true; idx[s] = bi; val[s] = bv; vs += bv;
        }
        float invs = 1.f / vs;
        for (int s = 0; s < TOPK; s++) {
            int e = idx[s];
            int pos = atomicAdd(&cnt[e], 1);
            gtok[(size_t)e * TT + pos] = t;
            gpid[(size_t)e * TT + pos] = t * TOPK + s;
            gpw [(size_t)e * TT + pos] = val[s] * invs;
        }
    }
}

__global__ void sig_k(const float* __restrict__ X, const float* __restrict__ Wshg,
                      float* __restrict__ sig) {
    int t = blockIdx.x;
    const float* x = X + (size_t)t * HH;
    float s = 0.f;
    for (int i = threadIdx.x; i < HH; i += blockDim.x) s += x[i] * Wshg[i];
    s = blockReduceSum(s);
    if (threadIdx.x == 0) sig[t] = 1.f / (1.f + expf(-s));
}

// float4-vectorized final combine
__global__ void final_k(const float* __restrict__ h, const float* __restrict__ ys,
                        const float* __restrict__ shr, const float* __restrict__ sig,
                        float* __restrict__ out) {
    long long i4 = (long long)blockIdx.x * 256 + threadIdx.x;   // float4 index
    if (i4 >= (long long)TT * HH / 4) return;
    long long base = i4 * 4;
    int t = (int)(base >> 11);
    int n = (int)(base & (HH - 1));
    float4 s = *(const float4*)(h + base);
    const float* yr = ys + ((long long)t * TOPK) * HH + n;
#pragma unroll
    for (int k = 0; k < TOPK; k++) {
        float4 y = *(const float4*)(yr + (long long)k * HH);
        s.x += y.x; s.y += y.y; s.z += y.z; s.w += y.w;
    }
    float sg = sig[t];
    float4 sh = *(const float4*)(shr + base);
    s.x += sh.x * sg; s.y += sh.y * sg; s.z += sh.z * sg; s.w += sh.w * sg;
    *(float4*)(out + base) = s;
}

// ================= TF32 tensor-core GEMM, cp.async 3-stage (R7-proven) =================
// BM=128, BN=128, BK=16, 256 threads (2m x 4n warps), warp tile 64x32.
#define LDAS 20
#define LDBS 132
#define NST  3
#define TMM_SMEM ((NST*128*LDAS + NST*16*LDBS)*4)

__global__ void __launch_bounds__(256, 2)
tmm_k(const float* __restrict__ A, const float* __restrict__ Bm,
      float* __restrict__ C, const float* __restrict__ addC,
      const int* __restrict__ rows, const float* __restrict__ wgt,
      const int* __restrict__ cnt, int Mfix,
      int N, int K, int lda, int ldc, long long bstride, long long cstrideZ,
      int listld) {
    extern __shared__ float sm[];
    float* As = sm;                        // [NST][128*LDAS]
    float* Bs = sm + NST * 128 * LDAS;     // [NST][16*LDBS]
    __shared__ int   rowIdx[128];
    __shared__ float rowW[128];

    int z = blockIdx.z;
    int mc = cnt ? cnt[z] : Mfix;
    int m0 = blockIdx.y * 128;
    if (m0 >= mc) return;
    int n0 = blockIdx.x * 128;
    const float* Bb = Bm + (long long)z * bstride;
    float* Cz = C + (long long)z * cstrideZ;
    const int*   rl = rows ? rows + (long long)z * listld : nullptr;
    const float* wl = wgt  ? wgt  + (long long)z * listld : nullptr;

    int tid = threadIdx.x;
    if (tid < 128) {
        int m = min(m0 + tid, mc - 1);
        rowIdx[tid] = rl ? rl[m] : m;
        rowW[tid]   = wl ? wl[m] : 1.f;
    }
    __syncthreads();

    int warp = tid >> 5, lane = tid & 31;
    int g = lane >> 2, tc = lane & 3;
    int warpM = (warp & 1) * 64, warpN = (warp >> 1) * 32;

    int aM = tid & 127, aKq = tid >> 7;
    int bR = tid >> 5,  bC = tid & 31;
    const float* aBase = A + (long long)rowIdx[aM] * lda;
    uint32_t asA = (uint32_t)__cvta_generic_to_shared(As);
    uint32_t bsA = (uint32_t)__cvta_generic_to_shared(Bs);
    uint32_t aS0 = asA + (uint32_t)(aM * LDAS + aKq * 4) * 4u;
    uint32_t aS1 = asA + (uint32_t)(aM * LDAS + (aKq + 2) * 4) * 4u;
    uint32_t bS0 = bsA + (uint32_t)(bR * LDBS + bC * 4) * 4u;
    uint32_t bS1 = bsA + (uint32_t)((bR + 8) * LDBS + bC * 4) * 4u;
    const uint32_t aStep = 128u * LDAS * 4u, bStep = 16u * LDBS * 4u;

    float acc[4][4][4] = {};
    int KT = K / 16;

#define TMM_ISSUE(kt, buf) { \
        int k0_ = (kt) * 16; \
        cp16(aS0 + (buf) * aStep, aBase + k0_ + aKq * 4); \
        cp16(aS1 + (buf) * aStep, aBase + k0_ + (aKq + 2) * 4); \
        cp16(bS0 + (buf) * bStep, Bb + (long long)(k0_ + bR) * N + n0 + bC * 4); \
        cp16(bS1 + (buf) * bStep, Bb + (long long)(k0_ + bR + 8) * N + n0 + bC * 4); \
        cp_commit(); }

    TMM_ISSUE(0, 0);
    TMM_ISSUE(1, 1);

    for (int kt = 0; kt < KT; kt++) {
        int nb = kt + NST - 1;
        if (nb < KT) { TMM_ISSUE(nb, nb % NST); cp_wait<NST - 2>(); }
        else cp_wait<0>();
        __syncthreads();
        const float* Ab2 = As + (kt % NST) * 128 * LDAS;
        const float* Bb2 = Bs + (kt % NST) * 16 * LDBS;
#pragma unroll
        for (int ks = 0; ks < 2; ks++) {
            uint32_t afr[4][4], bfr[4][2];
#pragma unroll
            for (int i = 0; i < 4; i++) {
                const float* ar = Ab2 + (warpM + i * 16 + g) * LDAS + ks * 8 + tc;
                afr[i][0] = __float_as_uint(tf32r(ar[0]));
                afr[i][1] = __float_as_uint(tf32r(ar[8 * LDAS]));
                afr[i][2] = __float_as_uint(tf32r(ar[4]));
                afr[i][3] = __float_as_uint(tf32r(ar[8 * LDAS + 4]));
            }
#pragma unroll
            for (int j = 0; j < 4; j++) {
                const float* br = Bb2 + (ks * 8 + tc) * LDBS + warpN + j * 8 + g;
                bfr[j][0] = __float_as_uint(tf32r(br[0]));
                bfr[j][1] = __float_as_uint(tf32r(br[4 * LDBS]));
            }
#pragma unroll
            for (int i = 0; i < 4; i++)
#pragma unroll
                for (int j = 0; j < 4; j++) mma_tf32(acc[i][j], afr[i], bfr[j]);
        }
        __syncthreads();
    }

#pragma unroll
    for (int i = 0; i < 4; i++) {
#pragma unroll
        for (int half = 0; half < 2; half++) {
            int rr = warpM + i * 16 + g + half * 8;
            if (m0 + rr >= mc) continue;
            int grow = rowIdx[rr];
            float w = rowW[rr];
            float* cp = Cz + (long long)grow * ldc + n0 + warpN + 2 * tc;
            const float* ap = addC ? addC + (long long)grow * ldc + n0 + warpN + 2 * tc : nullptr;
#pragma unroll
            for (int j = 0; j < 4; j++) {
                float v0 = acc[i][j][half * 2 + 0] * w;
                float v1 = acc[i][j][half * 2 + 1] * w;
                if (ap) {
                    float2 c0 = *(const float2*)(ap + j * 8);
                    v0 += c0.x; v1 += c0.y;
                }
                *(float2*)(cp + j * 8) = make_float2(v0, v1);
            }
        }
    }
}

// ================= TF32 grouped gate/up GEMM, cp.async 3-stage (R7-proven) =================
// BM=128, BN=64, BK=16, 256 threads (2m x 4n warps), warp tile 64x16.
#define LDBSG 68
#define TGU_SMEM ((NST*128*LDAS + NST*16*LDBSG*2)*4)

__global__ void __launch_bounds__(256, 2)
tgu_k(const float* __restrict__ X,
      const float* __restrict__ Wg, const float* __restrict__ Wu,
      float* __restrict__ Out,
      const int* __restrict__ gtok, const int* __restrict__ gpid,
      const int* __restrict__ cnt, int Mfix,
      int N, int K, long long wstride, int ldout, int listld) {
    extern __shared__ float sm[];
    float* As  = sm;                            // [NST][128*LDAS]
    float* Bgs = sm + NST * 128 * LDAS;         // [NST][16*LDBSG]
    float* Bus = Bgs + NST * 16 * LDBSG;        // [NST][16*LDBSG]
    __shared__ int rowTok[128];
    __shared__ int rowPid[128];

    int z = blockIdx.z;
    int mc = cnt ? cnt[z] : Mfix;
    int m0 = blockIdx.y * 128;
    if (m0 >= mc) return;
    int n0 = blockIdx.x * 64;
    const float* Wgb = Wg + (long long)z * wstride;
    const float* Wub = Wu + (long long)z * wstride;
    const int* lt = gtok + (long long)z * listld;
    const int* lp = gpid + (long long)z * listld;

    int tid = threadIdx.x;
    if (tid < 128) {
        int m = min(m0 + tid, mc - 1);
        rowTok[tid] = lt[m];
        rowPid[tid] = lp[m];
    }
    __syncthreads();

    int warp = tid >> 5, lane = tid & 31;
    int g = lane >> 2, tc = lane & 3;
    int warpM = (warp & 1) * 64, warpN = (warp >> 1) * 16;

    int aM = tid & 127, aKq = tid >> 7;
    int bR = tid >> 4, bC = tid & 15;
    const float* aBase = X + (long long)rowTok[aM] * K;
    uint32_t asA = (uint32_t)__cvta_generic_to_shared(As);
    uint32_t bgA = (uint32_t)__cvta_generic_to_shared(Bgs);
    uint32_t buA = (uint32_t)__cvta_generic_to_shared(Bus);
    uint32_t aS0 = asA + (uint32_t)(aM * LDAS + aKq * 4) * 4u;
    uint32_t aS1 = asA + (uint32_t)(aM * LDAS + (aKq + 2) * 4) * 4u;
    uint32_t bOf = (uint32_t)(bR * LDBSG + bC * 4) * 4u;
    const uint32_t aStep = 128u * LDAS * 4u, bStep = 16u * LDBSG * 4u;

    float accG[4][2][4] = {}, accU[4][2][4] = {};
    int KT = K / 16;

#define TGU_ISSUE(kt, buf) { \
        int k0_ = (kt) * 16; \
        cp16(aS0 + (buf) * aStep, aBase + k0_ + aKq * 4); \
        cp16(aS1 + (buf) * aStep, aBase + k0_ + (aKq + 2) * 4); \
        cp16(bgA + bOf + (buf) * bStep, Wgb + (long long)(k0_ + bR) * N + n0 + bC * 4); \
        cp16(buA + bOf + (buf) * bStep, Wub + (long long)(k0_ + bR) * N + n0 + bC * 4); \
        cp_commit(); }

    TGU_ISSUE(0, 0);
    TGU_ISSUE(1, 1);

    for (int kt = 0; kt < KT; kt++) {
        int nb = kt + NST - 1;
        if (nb < KT) { TGU_ISSUE(nb, nb % NST); cp_wait<NST - 2>(); }
        else cp_wait<0>();
        __syncthreads();
        const float* Ab2 = As + (kt % NST) * 128 * LDAS;
        const float* Bg2 = Bgs + (kt % NST) * 16 * LDBSG;
        const float* Bu2 = Bus + (kt % NST) * 16 * LDBSG;
#pragma unroll
        for (int ks = 0; ks < 2; ks++) {
            uint32_t afr[4][4], bgf[2][2], buf2[2][2];
#pragma unroll
            for (int i = 0; i < 4; i++) {
                const float* ar = Ab2 + (warpM + i * 16 + g) * LDAS + ks * 8 + tc;
                afr[i][0] = __float_as_uint(tf32r(ar[0]));
                afr[i][1] = __float_as_uint(tf32r(ar[8 * LDAS]));
                afr[i][2] = __float_as_uint(tf32r(ar[4]));
                afr[i][3] = __float_as_uint(tf32r(ar[8 * LDAS + 4]));
            }
#pragma unroll
            for (int j = 0; j < 2; j++) {
                const float* bgr = Bg2 + (ks * 8 + tc) * LDBSG + warpN + j * 8 + g;
                const float* bur = Bu2 + (ks * 8 + tc) * LDBSG + warpN + j * 8 + g;
                bgf[j][0] = __float_as_uint(tf32r(bgr[0]));
                bgf[j][1] = __float_as_uint(tf32r(bgr[4 * LDBSG]));
                buf2[j][0] = __float_as_uint(tf32r(bur[0]));
                buf2[j][1] = __float_as_uint(tf32r(bur[4 * LDBSG]));
            }
#pragma unroll
            for (int i = 0; i < 4; i++)
#pragma unroll
                for (int j = 0; j < 2; j++) {
                    mma_tf32(accG[i][j], afr[i], bgf[j]);
                    mma_tf32(accU[i][j], afr[i], buf2[j]);
                }
        }
        __syncthreads();
    }

#pragma unroll
    for (int i = 0; i < 4; i++) {
#pragma unroll
        for (int half = 0; half < 2; half++) {
            int rr = warpM + i * 16 + g + half * 8;
            if (m0 + rr >= mc) continue;
            int pid = rowPid[rr];
            float* op = Out + (long long)pid * ldout + n0 + warpN + 2 * tc;
#pragma unroll
            for (int j = 0; j < 2; j++) {
                float g0 = accG[i][j][half * 2 + 0], g1 = accG[i][j][half * 2 + 1];
                float u0 = accU[i][j][half * 2 + 0], u1 = accU[i][j][half * 2 + 1];
                float v0 = (g0 / (1.f + expf(-g0))) * u0;
                float v1 = (g1 / (1.f + expf(-g1))) * u1;
                *(float2*)(op + j * 8) = make_float2(v0, v1);
            }
        }
    }
}

// ================= Fused flash attention (tf32 MMA, online softmax) =================
// One block per (b, head, 128-query tile). 8 warps, each owns 16 query rows.
// KV tiles of 64 keys, double-buffered cp.async; causal.
#define FLDK 132
#define FLDP 68
#define FLASH_SMEM ((4*64*FLDK + 8*16*FLDP)*4)

__global__ void __launch_bounds__(256)
flash_k(const float* __restrict__ Q, const float* __restrict__ Kb,
        const float* __restrict__ Vb, float* __restrict__ O) {
    extern __shared__ float fs[];
    float* Ks = fs;                       // [2][64][FLDK]
    float* Vs = fs + 2 * 64 * FLDK;       // [2][64][FLDK]
    float* Ps = fs + 4 * 64 * FLDK;       // [8][16][FLDP]

    int bh = blockIdx.x;                  // b*NHQ + h
    int b = bh >> 5, hq = bh & 31;
    int kvh = hq >> 3;                    // GQA
    int qb = 7 - blockIdx.y;              // big tiles first
    int tid = threadIdx.x, w = tid >> 5, lane = tid & 31;
    int g = lane >> 2, tc = lane & 3;

    int row0 = qb * 128 + w * 16 + g;
    int row1 = row0 + 8;
    const float* q0 = Q + ((long long)(b * SS + row0) * NHQ + hq) * DH;
    const float* q1 = q0 + (long long)8 * NHQ * DH;
    const float* kbase = Kb + ((long long)b * SS * NKV + kvh) * DH;
    const float* vbase = Vb + ((long long)b * SS * NKV + kvh) * DH;
    uint32_t ksA = (uint32_t)__cvta_generic_to_shared(Ks);
    uint32_t vsA = (uint32_t)__cvta_generic_to_shared(Vs);

    const float scale = 0.08838834764831845f;   // D^-0.5, folded into Q
    uint32_t qf[16][4];
#pragma unroll
    for (int kk = 0; kk < 16; kk++) {
        qf[kk][0] = __float_as_uint(tf32r(q0[kk * 8 + tc] * scale));
        qf[kk][1] = __float_as_uint(tf32r(q1[kk * 8 + tc] * scale));
        qf[kk][2] = __float_as_uint(tf32r(q0[kk * 8 + tc + 4] * scale));
        qf[kk][3] = __float_as_uint(tf32r(q1[kk * 8 + tc + 4] * scale));
    }

    float o[16][4] = {};
    float m0 = -1e30f, m1 = -1e30f, l0 = 0.f, l1 = 0.f;
    float* Pw = Ps + w * 16 * FLDP;
    const float L2E = 1.4426950408889634f;

    int NT = (qb + 1) * 2;

#define FL_LOAD(n0_, buf_) { \
        _Pragma("unroll") \
        for (int p = 0; p < 8; p++) { \
            int c = tid + p * 256; \
            int r = c >> 5, cq = c & 31; \
            long long go = (long long)((n0_) + r) * (NKV * DH) + cq * 4; \
            uint32_t so = (uint32_t)((((buf_) * 64 + r) * FLDK + cq * 4) * 4); \
            cp16(ksA + so, kbase + go); \
            cp16(vsA + so, vbase + go); \
        } \
        cp_commit(); }

    FL_LOAD(0, 0);

    for (int jt = 0; jt < NT; jt++) {
        int n0 = jt * 64;
        if (jt + 1 < NT) { FL_LOAD((jt + 1) * 64, (jt + 1) & 1); cp_wait<1>(); }
        else cp_wait<0>();
        __syncthreads();

        float* Kt = Ks + (jt & 1) * 64 * FLDK;
        float* Vt = Vs + (jt & 1) * 64 * FLDK;
        // in-place tf32 conversion of the arrived tile
#pragma unroll
        for (int p = 0; p < 8; p++) {
            int c = tid + p * 256; int r = c >> 5, cq = c & 31;
            float4* kp = (float4*)(Kt + r * FLDK + cq * 4);
            float4* vp = (float4*)(Vt + r * FLDK + cq * 4);
            *kp = tf32r4(*kp);
            *vp = tf32r4(*vp);
        }
        __syncthreads();

        // S = Q K^T
        float s[8][4] = {};
#pragma unroll
        for (int kk = 0; kk < 16; kk++) {
#pragma unroll
            for (int j2 = 0; j2 < 8; j2++) {
                uint32_t bf[2];
                const float* kr = Kt + (j2 * 8 + g) * FLDK + kk * 8 + tc;
                bf[0] = __float_as_uint(kr[0]);
                bf[1] = __float_as_uint(kr[4]);
                mma_tf32(s[j2], qf[kk], bf);
            }
        }
        // causal mask for diagonal tiles
        if (n0 + 63 > qb * 128) {
#pragma unroll
            for (int j2 = 0; j2 < 8; j2++) {
                int k0 = n0 + j2 * 8 + 2 * tc;
                if (k0     > row0) s[j2][0] = -1e30f;
                if (k0 + 1 > row0) s[j2][1] = -1e30f;
                if (k0     > row1) s[j2][2] = -1e30f;
                if (k0 + 1 > row1) s[j2][3] = -1e30f;
            }
        }
        // online softmax (2 rows per thread)
        float tm0 = -1e30f, tm1 = -1e30f;
#pragma unroll
        for (int j2 = 0; j2 < 8; j2++) {
            tm0 = fmaxf(tm0, fmaxf(s[j2][0], s[j2][1]));
            tm1 = fmaxf(tm1, fmaxf(s[j2][2], s[j2][3]));
        }
        tm0 = fmaxf(tm0, __shfl_xor_sync(0xffffffffu, tm0, 1));
        tm0 = fmaxf(tm0, __shfl_xor_sync(0xffffffffu, tm0, 2));
        tm1 = fmaxf(tm1, __shfl_xor_sync(0xffffffffu, tm1, 1));
        tm1 = fmaxf(tm1, __shfl_xor_sync(0xffffffffu, tm1, 2));
        float mn0 = fmaxf(m0, tm0), mn1 = fmaxf(m1, tm1);
        float ts0 = 0.f, ts1 = 0.f;
#pragma unroll
        for (int j2 = 0; j2 < 8; j2++) {
            s[j2][0] = ex2f((s[j2][0] - mn0) * L2E);
            s[j2][1] = ex2f((s[j2][1] - mn0) * L2E);
            s[j2][2] = ex2f((s[j2][2] - mn1) * L2E);
            s[j2][3] = ex2f((s[j2][3] - mn1) * L2E);
            ts0 += s[j2][0] + s[j2][1];
            ts1 += s[j2][2] + s[j2][3];
        }
        ts0 += __shfl_xor_sync(0xffffffffu, ts0, 1);
        ts0 += __shfl_xor_sync(0xffffffffu, ts0, 2);
        ts1 += __shfl_xor_sync(0xffffffffu, ts1, 1);
        ts1 += __shfl_xor_sync(0xffffffffu, ts1, 2);
        float f0 = ex2f((m0 - mn0) * L2E), f1 = ex2f((m1 - mn1) * L2E);
        l0 = l0 * f0 + ts0; l1 = l1 * f1 + ts1;
        m0 = mn0; m1 = mn1;
#pragma unroll
        for (int j3 = 0; j3 < 16; j3++) {
            o[j3][0] *= f0; o[j3][1] *= f0; o[j3][2] *= f1; o[j3][3] *= f1;
        }
        // P -> smem (tf32), then O += P V
#pragma unroll
        for (int j2 = 0; j2 < 8; j2++) {
            Pw[g * FLDP + j2 * 8 + 2 * tc]           = tf32r(s[j2][0]);
            Pw[g * FLDP + j2 * 8 + 2 * tc + 1]       = tf32r(s[j2][1]);
            Pw[(g + 8) * FLDP + j2 * 8 + 2 * tc]     = tf32r(s[j2][2]);
            Pw[(g + 8) * FLDP + j2 * 8 + 2 * tc + 1] = tf32r(s[j2][3]);
        }
        __syncwarp();
#pragma unroll
        for (int kk2 = 0; kk2 < 8; kk2++) {
            uint32_t af[4];
            af[0] = __float_as_uint(Pw[g * FLDP + kk2 * 8 + tc]);
            af[1] = __float_as_uint(Pw[(g + 8) * FLDP + kk2 * 8 + tc]);
            af[2] = __float_as_uint(Pw[g * FLDP + kk2 * 8 + tc + 4]);
            af[3] = __float_as_uint(Pw[(g + 8) * FLDP + kk2 * 8 + tc + 4]);
#pragma unroll
            for (int j3 = 0; j3 < 16; j3++) {
                uint32_t bf[2];
                bf[0] = __float_as_uint(Vt[(kk2 * 8 + tc) * FLDK + j3 * 8 + g]);
                bf[1] = __float_as_uint(Vt[(kk2 * 8 + tc + 4) * FLDK + j3 * 8 + g]);
                mma_tf32(o[j3], af, bf);
            }
        }
        __syncwarp();
        __syncthreads();
    }

    float il0 = 1.f / l0, il1 = 1.f / l1;
    float* o0 = O + ((long long)(b * SS + row0) * NHQ + hq) * DH;
    float* o1 = o0 + (long long)8 * NHQ * DH;
#pragma unroll
    for (int j3 = 0; j3 < 16; j3++) {
        *(float2*)(o0 + j3 * 8 + 2 * tc) = make_float2(o[j3][0] * il0, o[j3][1] * il0);
        *(float2*)(o1 + j3 * 8 + 2 * tc) = make_float2(o[j3][2] * il1, o[j3][3] * il1);
    }
}

// ---------------- host ----------------
extern "C" void kernel_launch(void* const* d_in, const int* in_sizes, int n_in,
                              void* d_out, int out_size) {
    const float* hidden = (const float*)d_in[0];
    const float* ln1w   = (const float*)d_in[1];
    const float* ln2w   = (const float*)d_in[2];
    const float* qnw    = (const float*)d_in[3];
    const float* knw    = (const float*)d_in[4];
    const float* Wq     = (const float*)d_in[5];
    const float* Wk     = (const float*)d_in[6];
    const float* Wv     = (const float*)d_in[7];
    const float* Wo     = (const float*)d_in[8];
    const float* Wr     = (const float*)d_in[9];
    const float* Weg    = (const float*)d_in[10];
    const float* Weu    = (const float*)d_in[11];
    const float* Wed    = (const float*)d_in[12];
    const float* Wsg    = (const float*)d_in[13];
    const float* Wsu    = (const float*)d_in[14];
    const float* Wsd    = (const float*)d_in[15];
    const float* Wshg   = (const float*)d_in[16];
    float* out = (float*)d_out;

    float *x, *q, *kb, *vb, *o, *h, *x2, *act, *ys, *acts, *shr, *sig, *pw, *cosT, *sinT;
    int *cnt, *cntT, *ptok, *ppid, *idl;
    cudaGetSymbolAddress((void**)&x,    g_x);
    cudaGetSymbolAddress((void**)&q,    g_q);
    cudaGetSymbolAddress((void**)&kb,   g_kbuf);
    cudaGetSymbolAddress((void**)&vb,   g_vbuf);
    cudaGetSymbolAddress((void**)&o,    g_o);
    cudaGetSymbolAddress((void**)&h,    g_h);
    cudaGetSymbolAddress((void**)&x2,   g_x2);
    cudaGetSymbolAddress((void**)&act,  g_act);
    cudaGetSymbolAddress((void**)&ys,   g_ys);
    cudaGetSymbolAddress((void**)&acts, g_acts);
    cudaGetSymbolAddress((void**)&shr,  g_shr);
    cudaGetSymbolAddress((void**)&sig,  g_sig);
    cudaGetSymbolAddress((void**)&pw,   g_pw);
    cudaGetSymbolAddress((void**)&cosT, g_cosT);
    cudaGetSymbolAddress((void**)&sinT, g_sinT);
    cudaGetSymbolAddress((void**)&cnt,  g_cnt);
    cudaGetSymbolAddress((void**)&cntT, g_cntT);
    cudaGetSymbolAddress((void**)&ptok, g_ptok);
    cudaGetSymbolAddress((void**)&ppid, g_ppid);
    cudaGetSymbolAddress((void**)&idl,  g_idl);

    cudaFuncSetAttribute(tmm_k,   cudaFuncAttributeMaxDynamicSharedMemorySize, TMM_SMEM);
    cudaFuncSetAttribute(tgu_k,   cudaFuncAttributeMaxDynamicSharedMemorySize, TGU_SMEM);
    cudaFuncSetAttribute(flash_k, cudaFuncAttributeMaxDynamicSharedMemorySize, FLASH_SMEM);

    // runtime strides for fused K+V projection (flat device address space)
    long long kvB = (long long)((const char*)Wv - (const char*)Wk) / 4;
    long long kvC = (long long)((char*)vb - (char*)kb) / 4;

    // 0) rope LUT (same expressions as before — bitwise-identical values)
    rope_tab_k<<<(SS * DH + 255) / 256, 256>>>(cosT, sinT);
    // 1) ln1
    rmsnorm_k<<<TT, 256>>>(hidden, ln1w, x, HH);
    // 2) q + fused k/v projections (tf32 tensor cores, 3-stage cp.async pipeline)
    tmm_k<<<dim3(32, 32, 1), 256, TMM_SMEM>>>(x, Wq, q, nullptr, nullptr, nullptr, nullptr, TT,
        NHQ * DH, HH, HH, NHQ * DH, 0, 0, 0);
    tmm_k<<<dim3(4, 32, 2), 256, TMM_SMEM>>>(x, Wk, kb, nullptr, nullptr, nullptr, nullptr, TT,
        NKV * DH, HH, HH, NKV * DH, kvB, kvC, 0);
    // 3) q/k rmsnorm + rope (LUT)
    qknorm_rope_k<<<TT * NHQ, DH>>>(q, qnw, cosT, sinT, NHQ);
    qknorm_rope_k<<<TT * NKV, DH>>>(kb, knw, cosT, sinT, NKV);
    // 4-6) fused flash attention (causal, online softmax)
    flash_k<<<dim3(BB * NHQ, 8), 256, FLASH_SMEM>>>(q, kb, vb, o);
    // 7) h = hidden + o @ Wo (tf32)
    tmm_k<<<dim3(16, 32, 1), 256, TMM_SMEM>>>(o, Wo, h, hidden, nullptr, nullptr, nullptr, TT,
        HH, NHQ * DH, NHQ * DH, HH, 0, 0, 0);
    // 8) ln2
    rmsnorm_k<<<TT, 256>>>(h, ln2w, x2, HH);
    // 9) routing
    cudaMemsetAsync(cnt, 0, NE * sizeof(int), 0);
    init_k<<<TT / 256, 256>>>(idl, cntT);
    router_k<<<TT, 128>>>(x2, Wr, cnt, ptok, ppid, pw);
    // 10) MoE experts (tf32): gate/up (silu fused) then down (weighted, per-slot)
    tgu_k<<<dim3(II / 64, 32, NE), 256, TGU_SMEM>>>(x2, Weg, Weu, act, ptok, ppid, cnt, 0,
        II, HH, (long long)HH * II, II, TT);
    tmm_k<<<dim3(HH / 128, 32, NE), 256, TMM_SMEM>>>(act, Wed, ys, nullptr, ppid, pw, cnt, 0,
        HH, II, II, HH, (long long)II * HH, 0, TT);
    // 11) shared expert (tf32) via identity lists
    tgu_k<<<dim3(ISD / 64, 32, 1), 256, TGU_SMEM>>>(x2, Wsg, Wsu, acts, idl, idl, cntT, 0,
        ISD, HH, 0, ISD, TT);
    tmm_k<<<dim3(HH / 128, 32, 1), 256, TMM_SMEM>>>(acts, Wsd, shr, nullptr, idl, nullptr, cntT, 0,
        HH, ISD, ISD, HH, 0, 0, TT);
    sig_k<<<TT, 256>>>(x2, Wshg, sig);
    // 12) out = h + sum(slots) + shared*sigmoid
    final_k<<<(TT * HH / 4 + 255) / 256, 256>>>(h, ys, shr, sig, out);
}